// round 1
// baseline (speedup 1.0000x reference)
#include <cuda_runtime.h>
#include <math.h>

#define KM 16
#define DM 16

// Precomputed per-mixture data (device scratch; no allocations allowed).
__device__ float g_M[KM][DM][DM];   // M = L^{-1}, lower triangular (Sigma = L L^T)
__device__ float g_v[KM][DM];       // v = M @ mu
__device__ float g_c[KM];           // Phi / sqrt(2*pi*det(Sigma))

// ---------------------------------------------------------------------------
// Precompute kernel: one thread per mixture. Cholesky + triangular inverse.
// K=16 mixtures of 16x16 — trivial cost, spills to local, doesn't matter.
// ---------------------------------------------------------------------------
__global__ void gmm_precompute(const float* __restrict__ Phi,
                               const float* __restrict__ mu,
                               const float* __restrict__ Sigma) {
    int k = threadIdx.x;
    if (k >= KM) return;

    float A[DM][DM];
    for (int i = 0; i < DM; i++)
        for (int j = 0; j < DM; j++)
            A[i][j] = Sigma[(k * DM + i) * DM + j];

    // Cholesky: A(lower) <- L with Sigma = L L^T
    for (int i = 0; i < DM; i++) {
        for (int j = 0; j <= i; j++) {
            float s = A[i][j];
            for (int p = 0; p < j; p++) s -= A[i][p] * A[j][p];
            if (i == j) A[i][i] = sqrtf(s);
            else        A[i][j] = s / A[j][j];
        }
    }

    float det = 1.0f;
    for (int i = 0; i < DM; i++) det *= A[i][i] * A[i][i];

    // Mi = L^{-1} (forward substitution per column)
    float Mi[DM][DM];
    for (int i = 0; i < DM; i++)
        for (int j = 0; j < DM; j++) Mi[i][j] = 0.0f;
    for (int i = 0; i < DM; i++) {
        Mi[i][i] = 1.0f / A[i][i];
        for (int j = 0; j < i; j++) {
            float s = 0.0f;
            for (int p = j; p < i; p++) s += A[i][p] * Mi[p][j];
            Mi[i][j] = -s / A[i][i];
        }
    }

    for (int i = 0; i < DM; i++) {
        float v = 0.0f;
        for (int j = 0; j <= i; j++) v += Mi[i][j] * mu[k * DM + j];
        g_v[k][i] = v;
        for (int j = 0; j < DM; j++) g_M[k][i][j] = Mi[i][j];
    }
    g_c[k] = Phi[k] * rsqrtf(2.0f * 3.14159265358979323846f * det);
}

// ---------------------------------------------------------------------------
// Main kernel: 4 samples per thread via packed f32x2 FMA.
// ---------------------------------------------------------------------------
typedef unsigned long long u64;

__device__ __forceinline__ u64 fma2(u64 a, u64 b, u64 c) {
    u64 r;
    asm("fma.rn.f32x2 %0, %1, %2, %3;" : "=l"(r) : "l"(a), "l"(b), "l"(c));
    return r;
}
__device__ __forceinline__ u64 pack2(float lo, float hi) {
    u64 r;
    asm("mov.b64 %0, {%1, %2};" : "=l"(r) : "f"(lo), "f"(hi));
    return r;
}
__device__ __forceinline__ void unpack2(u64 v, float& lo, float& hi) {
    asm("mov.b64 {%0, %1}, %2;" : "=f"(lo), "=f"(hi) : "l"(v));
}

__device__ __forceinline__ float gmm_scalar_one(const float* __restrict__ samples,
                                                long n) {
    float d[DM];
    for (int j = 0; j < DM; j++) d[j] = samples[n * DM + j];
    float pdf = 0.0f;
    for (int k = 0; k < KM; k++) {
        float quad = 0.0f;
        for (int i = 0; i < DM; i++) {
            float z = -g_v[k][i];
            for (int j = 0; j <= i; j++) z = fmaf(g_M[k][i][j], d[j], z);
            quad = fmaf(z, z, quad);
        }
        pdf += g_c[k] * __expf(-0.5f * quad);
    }
    return -logf(pdf);
}

__global__ __launch_bounds__(256, 2)
void gmm_main(const float4* __restrict__ samples4,
              const float* __restrict__ samples,
              float* __restrict__ out, int N) {
    __shared__ u64   sM2[KM][DM][DM];   // packed (m, m)         32 KB
    __shared__ u64   svn2[KM][DM];      // packed (-v, -v)        2 KB
    __shared__ float sc[KM];

    const float* gM = &g_M[0][0][0];
    for (int idx = threadIdx.x; idx < KM * DM * DM; idx += 256) {
        float m = gM[idx];
        ((u64*)sM2)[idx] = pack2(m, m);
    }
    const float* gv = &g_v[0][0];
    for (int idx = threadIdx.x; idx < KM * DM; idx += 256) {
        float v = gv[idx];
        ((u64*)svn2)[idx] = pack2(-v, -v);
    }
    if (threadIdx.x < KM) sc[threadIdx.x] = g_c[threadIdx.x];
    __syncthreads();

    long t = (long)blockIdx.x * blockDim.x + threadIdx.x;
    long base = t * 4;
    if (base >= N) return;

    if (base + 4 <= N) {
        // Fast path: 4 samples as 2 packed pairs.
        u64 d2[2][DM];
        #pragma unroll
        for (int p = 0; p < 2; p++) {
            float r0[DM], r1[DM];
            #pragma unroll
            for (int q = 0; q < 4; q++) {
                float4 a = samples4[(base + 2 * p) * 4 + q];
                r0[4*q+0] = a.x; r0[4*q+1] = a.y; r0[4*q+2] = a.z; r0[4*q+3] = a.w;
                float4 b = samples4[(base + 2 * p + 1) * 4 + q];
                r1[4*q+0] = b.x; r1[4*q+1] = b.y; r1[4*q+2] = b.z; r1[4*q+3] = b.w;
            }
            #pragma unroll
            for (int j = 0; j < DM; j++) d2[p][j] = pack2(r0[j], r1[j]);
        }

        float pdf0 = 0.0f, pdf1 = 0.0f, pdf2 = 0.0f, pdf3 = 0.0f;

        #pragma unroll 1
        for (int k = 0; k < KM; k++) {
            u64 quadA = 0ull;   // (0.0f, 0.0f)
            u64 quadB = 0ull;
            #pragma unroll
            for (int i = 0; i < DM; i++) {
                u64 zA = svn2[k][i];
                u64 zB = zA;
                #pragma unroll
                for (int j = 0; j <= i; j++) {
                    u64 m2 = sM2[k][i][j];
                    zA = fma2(m2, d2[0][j], zA);
                    zB = fma2(m2, d2[1][j], zB);
                }
                quadA = fma2(zA, zA, quadA);
                quadB = fma2(zB, zB, quadB);
            }
            float q0, q1, q2, q3;
            unpack2(quadA, q0, q1);
            unpack2(quadB, q2, q3);
            float c = sc[k];
            pdf0 += c * __expf(-0.5f * q0);
            pdf1 += c * __expf(-0.5f * q1);
            pdf2 += c * __expf(-0.5f * q2);
            pdf3 += c * __expf(-0.5f * q3);
        }
        out[base + 0] = -logf(pdf0);
        out[base + 1] = -logf(pdf1);
        out[base + 2] = -logf(pdf2);
        out[base + 3] = -logf(pdf3);
    } else {
        // Tail: scalar fallback (N=524288 is divisible by 4, but be safe).
        for (long n = base; n < N; n++)
            out[n] = gmm_scalar_one(samples, n);
    }
}

// ---------------------------------------------------------------------------
extern "C" void kernel_launch(void* const* d_in, const int* in_sizes, int n_in,
                              void* d_out, int out_size) {
    const float* samples = (const float*)d_in[0];
    const float* Phi     = (const float*)d_in[1];
    const float* mu      = (const float*)d_in[2];
    const float* Sigma   = (const float*)d_in[3];
    int N = in_sizes[0] / DM;

    gmm_precompute<<<1, KM>>>(Phi, mu, Sigma);

    int threads = (N + 3) / 4;
    int blocks  = (threads + 255) / 256;
    gmm_main<<<blocks, 256>>>((const float4*)samples, samples, (float*)d_out, N);
}

// round 2
// speedup vs baseline: 1.2588x; 1.2588x over previous
#include <cuda_runtime.h>
#include <math.h>

#define KM 16
#define DM 16

__device__ float g_M[KM][DM][DM];   // M = L^{-1}, lower triangular (zeros above diag)
__device__ float g_v[KM][DM];       // v = M @ mu
__device__ float g_c[KM];           // Phi / sqrt(2*pi*det(Sigma))

// ---------------------------------------------------------------------------
// Parallel precompute: 1 block, 256 threads = 16 mixtures x 16 lanes.
// Cholesky (row-parallel) + triangular inverse (column-parallel), in shared.
// ---------------------------------------------------------------------------
__global__ void gmm_precompute(const float* __restrict__ Phi,
                               const float* __restrict__ mu,
                               const float* __restrict__ Sigma) {
    __shared__ float L[KM][DM][DM + 1];
    __shared__ float Mi[KM][DM][DM + 1];

    int k = threadIdx.x >> 4;      // mixture
    int r = threadIdx.x & 15;      // lane within mixture (row / column id)

    // Load Sigma row r of mixture k
    for (int j = 0; j < DM; j++)
        L[k][r][j] = Sigma[(k * DM + r) * DM + j];
    __syncthreads();

    // Left-looking Cholesky: at pivot p, columns <p are final L, column p holds A.
    for (int p = 0; p < DM; p++) {
        if (r == p) {
            float s = L[k][p][p];
            for (int q = 0; q < p; q++) s -= L[k][p][q] * L[k][p][q];
            L[k][p][p] = sqrtf(s);
        }
        __syncthreads();
        if (r > p) {
            float s = L[k][r][p];
            for (int q = 0; q < p; q++) s -= L[k][r][q] * L[k][p][q];
            L[k][r][p] = s / L[k][p][p];
        }
        __syncthreads();
    }

    // Triangular inverse: thread (k, c) computes column c of Mi = L^{-1}.
    {
        int c = r;
        for (int i = 0; i < c; i++) Mi[k][i][c] = 0.0f;   // above diagonal
        Mi[k][c][c] = 1.0f / L[k][c][c];
        for (int i = c + 1; i < DM; i++) {
            float s = 0.0f;
            for (int q = c; q < i; q++) s += L[k][i][q] * Mi[k][q][c];
            Mi[k][i][c] = -s / L[k][i][i];
        }
    }
    __syncthreads();

    // v = Mi @ mu (thread r computes component r); write out row r of Mi.
    {
        float v = 0.0f;
        for (int j = 0; j <= r; j++) v += Mi[k][r][j] * mu[k * DM + j];
        g_v[k][r] = v;
        for (int j = 0; j < DM; j++) g_M[k][r][j] = Mi[k][r][j];
    }
    if (r == 0) {
        float prod = 1.0f;
        for (int i = 0; i < DM; i++) prod *= L[k][i][i];   // sqrt(det(Sigma))
        g_c[k] = Phi[k] / (sqrtf(2.0f * 3.14159265358979323846f) * prod);
    }
}

// ---------------------------------------------------------------------------
// Main kernel: 4 samples per thread via packed f32x2 FMA, LDS.128 matrix loads.
// ---------------------------------------------------------------------------
typedef unsigned long long u64;

__device__ __forceinline__ u64 fma2(u64 a, u64 b, u64 c) {
    u64 r;
    asm("fma.rn.f32x2 %0, %1, %2, %3;" : "=l"(r) : "l"(a), "l"(b), "l"(c));
    return r;
}
__device__ __forceinline__ u64 pack2(float lo, float hi) {
    u64 r;
    asm("mov.b64 %0, {%1, %2};" : "=l"(r) : "f"(lo), "f"(hi));
    return r;
}
__device__ __forceinline__ void unpack2(u64 v, float& lo, float& hi) {
    asm("mov.b64 {%0, %1}, %2;" : "=f"(lo), "=f"(hi) : "l"(v));
}

__device__ __forceinline__ float gmm_scalar_one(const float* __restrict__ samples,
                                                long n) {
    float d[DM];
    for (int j = 0; j < DM; j++) d[j] = samples[n * DM + j];
    float pdf = 0.0f;
    for (int k = 0; k < KM; k++) {
        float quad = 0.0f;
        for (int i = 0; i < DM; i++) {
            float z = -g_v[k][i];
            for (int j = 0; j <= i; j++) z = fmaf(g_M[k][i][j], d[j], z);
            quad = fmaf(z, z, quad);
        }
        pdf += g_c[k] * __expf(-0.5f * quad);
    }
    return -logf(pdf);
}

__global__ __launch_bounds__(256, 2)
void gmm_main(const float4* __restrict__ samples4,
              const float* __restrict__ samples,
              float* __restrict__ out, int N) {
    __shared__ u64   sM2[KM][DM][DM];   // packed (m, m); zeros above diagonal. 32 KB
    __shared__ u64   svn2[KM][DM];      // packed (-v, -v)                       2 KB
    __shared__ float sc[KM];

    const float* gM = &g_M[0][0][0];
    for (int idx = threadIdx.x; idx < KM * DM * DM; idx += 256) {
        float m = gM[idx];
        ((u64*)sM2)[idx] = pack2(m, m);
    }
    const float* gv = &g_v[0][0];
    for (int idx = threadIdx.x; idx < KM * DM; idx += 256) {
        float v = gv[idx];
        ((u64*)svn2)[idx] = pack2(-v, -v);
    }
    if (threadIdx.x < KM) sc[threadIdx.x] = g_c[threadIdx.x];
    __syncthreads();

    long t = (long)blockIdx.x * blockDim.x + threadIdx.x;
    long base = t * 4;
    if (base >= N) return;

    if (base + 4 <= N) {
        // 4 samples as 2 packed pairs.
        u64 d2[2][DM];
        #pragma unroll
        for (int p = 0; p < 2; p++) {
            float r0[DM], r1[DM];
            #pragma unroll
            for (int q = 0; q < 4; q++) {
                float4 a = samples4[(base + 2 * p) * 4 + q];
                r0[4*q+0] = a.x; r0[4*q+1] = a.y; r0[4*q+2] = a.z; r0[4*q+3] = a.w;
                float4 b = samples4[(base + 2 * p + 1) * 4 + q];
                r1[4*q+0] = b.x; r1[4*q+1] = b.y; r1[4*q+2] = b.z; r1[4*q+3] = b.w;
            }
            #pragma unroll
            for (int j = 0; j < DM; j++) d2[p][j] = pack2(r0[j], r1[j]);
        }

        float pdf0 = 0.0f, pdf1 = 0.0f, pdf2 = 0.0f, pdf3 = 0.0f;

        #pragma unroll 1
        for (int k = 0; k < KM; k++) {
            u64 quadA = 0ull;
            u64 quadB = 0ull;
            #pragma unroll
            for (int i = 0; i < DM; i++) {
                u64 zA = svn2[k][i];
                u64 zB = zA;
                // Row length padded to even: for even i the entry at j=i+1 is the
                // above-diagonal zero, so the extra FMA is a no-op. LDS.128 loads.
                const int rlen = (i & 1) ? (i + 1) : (i + 2);
                #pragma unroll
                for (int j = 0; j < rlen; j += 2) {
                    ulonglong2 m2 = *(const ulonglong2*)&sM2[k][i][j];
                    zA = fma2(m2.x, d2[0][j],     zA);
                    zA = fma2(m2.y, d2[0][j + 1], zA);
                    zB = fma2(m2.x, d2[1][j],     zB);
                    zB = fma2(m2.y, d2[1][j + 1], zB);
                }
                quadA = fma2(zA, zA, quadA);
                quadB = fma2(zB, zB, quadB);
            }
            float q0, q1, q2, q3;
            unpack2(quadA, q0, q1);
            unpack2(quadB, q2, q3);
            float c = sc[k];
            pdf0 += c * __expf(-0.5f * q0);
            pdf1 += c * __expf(-0.5f * q1);
            pdf2 += c * __expf(-0.5f * q2);
            pdf3 += c * __expf(-0.5f * q3);
        }
        float4 o;
        o.x = -logf(pdf0); o.y = -logf(pdf1);
        o.z = -logf(pdf2); o.w = -logf(pdf3);
        *(float4*)&out[base] = o;
    } else {
        for (long n = base; n < N; n++)
            out[n] = gmm_scalar_one(samples, n);
    }
}

// ---------------------------------------------------------------------------
extern "C" void kernel_launch(void* const* d_in, const int* in_sizes, int n_in,
                              void* d_out, int out_size) {
    const float* samples = (const float*)d_in[0];
    const float* Phi     = (const float*)d_in[1];
    const float* mu      = (const float*)d_in[2];
    const float* Sigma   = (const float*)d_in[3];
    int N = in_sizes[0] / DM;

    gmm_precompute<<<1, 256>>>(Phi, mu, Sigma);

    int threads = (N + 3) / 4;
    int blocks  = (threads + 255) / 256;
    gmm_main<<<blocks, 256>>>((const float4*)samples, samples, (float*)d_out, N);
}